// round 2
// baseline (speedup 1.0000x reference)
#include <cuda_runtime.h>
#include <math.h>

// Problem constants
#define BB 4
#define SS 2048
#define DD 2048
constexpr int BM = 128, BN = 128, BK = 16, TM = 8, TN = 8;

// Scratch (device globals — no allocations allowed)
__device__ float g_Q[(size_t)BB * SS * DD];
__device__ float g_K[(size_t)BB * SS * DD];
__device__ float g_V[(size_t)BB * SS * DD];
__device__ float g_P[(size_t)BB * SS * SS];
__device__ float g_C[(size_t)BB * SS * DD];

// ---------------------------------------------------------------------------
// Tiled GEMM.
//   TB=true : C[m,n] = sum_k A[m,k] * Bm[n,k]   (A:[M,K] k-contig, B:[N,K] k-contig)
//   TB=false: C[m,n] = sum_k A[m,k] * Bm[k,n]   (B:[K,N] n-contig)
// Optional bias (per-n), per-batch strides via blockIdx.z, causal mask+scale
// epilogue, and triangular K-limit (kEnd = m0 + BM) for the PV GEMM.
// ---------------------------------------------------------------------------
template <bool TB>
__global__ __launch_bounds__(256) void gemm_kernel(
    const float* __restrict__ A, const float* __restrict__ Bm,
    const float* __restrict__ bias, float* __restrict__ C,
    int M, int N, int K,
    long long strideA, long long strideB, long long strideC,
    float scale, int causal, int triK)
{
    const int b = blockIdx.z;
    A += (long long)b * strideA;
    Bm += (long long)b * strideB;
    C += (long long)b * strideC;

    const int m0 = blockIdx.y * BM;
    const int n0 = blockIdx.x * BN;
    if (causal && n0 > m0 + BM - 1) return;  // fully above diagonal

    int kEnd = K;
    if (triK) kEnd = min(K, m0 + BM);

    __shared__ float As[BK][BM + 4];
    __shared__ float Bs[BK][BN + 4];

    const int t = threadIdx.x;
    const int tx = t % 16;   // n direction
    const int ty = t / 16;   // m direction

    float acc[TM][TN];
#pragma unroll
    for (int i = 0; i < TM; i++)
#pragma unroll
        for (int j = 0; j < TN; j++) acc[i][j] = 0.f;

    for (int k0 = 0; k0 < kEnd; k0 += BK) {
        // Load A tile [BM x BK] (k-contiguous), store transposed As[k][m]
        {
            const int f = t % 4;       // float4 index within BK
            const int r = t / 4;       // 0..63
#pragma unroll
            for (int p = 0; p < 2; p++) {
                const int row = p * 64 + r;
                float4 v = *reinterpret_cast<const float4*>(
                    &A[(long long)(m0 + row) * K + k0 + f * 4]);
                As[f * 4 + 0][row] = v.x;
                As[f * 4 + 1][row] = v.y;
                As[f * 4 + 2][row] = v.z;
                As[f * 4 + 3][row] = v.w;
            }
        }
        if (TB) {
            const int f = t % 4;
            const int r = t / 4;
#pragma unroll
            for (int p = 0; p < 2; p++) {
                const int row = p * 64 + r;
                float4 v = *reinterpret_cast<const float4*>(
                    &Bm[(long long)(n0 + row) * K + k0 + f * 4]);
                Bs[f * 4 + 0][row] = v.x;
                Bs[f * 4 + 1][row] = v.y;
                Bs[f * 4 + 2][row] = v.z;
                Bs[f * 4 + 3][row] = v.w;
            }
        } else {
            const int c = t % 32;      // float4 column index
            const int kr = t / 32;     // 0..7
#pragma unroll
            for (int p = 0; p < 2; p++) {
                const int kk = p * 8 + kr;
                float4 v = *reinterpret_cast<const float4*>(
                    &Bm[(long long)(k0 + kk) * N + n0 + c * 4]);
                *reinterpret_cast<float4*>(&Bs[kk][c * 4]) = v;
            }
        }
        __syncthreads();

#pragma unroll
        for (int kk = 0; kk < BK; kk++) {
            float ra[TM], rb[TN];
#pragma unroll
            for (int i = 0; i < TM; i++) ra[i] = As[kk][ty * TM + i];
#pragma unroll
            for (int j = 0; j < TN; j++) rb[j] = Bs[kk][tx * TN + j];
#pragma unroll
            for (int i = 0; i < TM; i++)
#pragma unroll
                for (int j = 0; j < TN; j++) acc[i][j] = fmaf(ra[i], rb[j], acc[i][j]);
        }
        __syncthreads();
    }

    // Epilogue
#pragma unroll
    for (int i = 0; i < TM; i++) {
        const int gi = m0 + ty * TM + i;
#pragma unroll
        for (int j = 0; j < TN; j++) {
            const int gj = n0 + tx * TN + j;
            float v = acc[i][j] * scale;
            if (bias) v += bias[gj];
            if (causal && gj > gi) v = 0.f;  // above-diagonal in diagonal tile
            C[(long long)gi * N + gj] = v;
        }
    }
}

// ---------------------------------------------------------------------------
// RoPE: rotate (i, i+half) pairs of both Q and K in place.
// ---------------------------------------------------------------------------
__global__ void rope_kernel(float* __restrict__ Q, float* __restrict__ Kt)
{
    const int half = DD / 2;
    long long idx = (long long)blockIdx.x * blockDim.x + threadIdx.x;
    const long long total = (long long)BB * SS * half;
    if (idx >= total) return;

    const int i = (int)(idx % half);
    const long long bs = idx / half;
    const int s = (int)(bs % SS);

    // inv_freq = 10000^(-i/half); compute angle in double then fp32 sincos
    const double invf = exp(-(double)i * (9.210340371976184 / (double)half));
    const float ang = (float)((double)s * invf);
    float sn, cs;
    sincosf(ang, &sn, &cs);

    float* q = Q + bs * DD;
    float* k = Kt + bs * DD;

    const float q1 = q[i], q2 = q[i + half];
    q[i] = q1 * cs - q2 * sn;
    q[i + half] = q1 * sn + q2 * cs;

    const float k1 = k[i], k2 = k[i + half];
    k[i] = k1 * cs - k2 * sn;
    k[i + half] = k1 * sn + k2 * cs;
}

// ---------------------------------------------------------------------------
// Causal row softmax over j <= i, then zero-fill (i, kend) so PV GEMM can run
// with a per-tile triangular K limit.
// ---------------------------------------------------------------------------
__inline__ __device__ float warpMax(float v)
{
    for (int o = 16; o; o >>= 1) v = fmaxf(v, __shfl_xor_sync(0xffffffffu, v, o));
    return v;
}
__inline__ __device__ float warpSum(float v)
{
    for (int o = 16; o; o >>= 1) v += __shfl_xor_sync(0xffffffffu, v, o);
    return v;
}

__global__ __launch_bounds__(256) void softmax_kernel(float* __restrict__ P)
{
    const int i = blockIdx.x;   // row within batch
    const int b = blockIdx.y;
    float* row = P + ((long long)b * SS + i) * SS;
    const int len = i + 1;
    const int t = threadIdx.x;
    const int lane = t & 31, w = t >> 5;

    __shared__ float sh[8];
    __shared__ float s_bcast;

    // max
    float m = -INFINITY;
    for (int j = t; j < len; j += 256) m = fmaxf(m, row[j]);
    m = warpMax(m);
    if (lane == 0) sh[w] = m;
    __syncthreads();
    if (t == 0) {
        float mm = sh[0];
        for (int k = 1; k < 8; k++) mm = fmaxf(mm, sh[k]);
        s_bcast = mm;
    }
    __syncthreads();
    m = s_bcast;
    __syncthreads();

    // sum of exp
    float sum = 0.f;
    for (int j = t; j < len; j += 256) sum += expf(row[j] - m);
    sum = warpSum(sum);
    if (lane == 0) sh[w] = sum;
    __syncthreads();
    if (t == 0) {
        float ss = 0.f;
        for (int k = 0; k < 8; k++) ss += sh[k];
        s_bcast = ss;
    }
    __syncthreads();
    const float inv = 1.f / s_bcast;

    // normalize + zero-fill to 128-aligned boundary
    for (int j = t; j < len; j += 256) row[j] = expf(row[j] - m) * inv;
    const int kend = ((i >> 7) + 1) << 7;
    for (int j = len + t; j < kend; j += 256) row[j] = 0.f;
}

// ---------------------------------------------------------------------------
extern "C" void kernel_launch(void* const* d_in, const int* in_sizes, int n_in,
                              void* d_out, int out_size)
{
    const float* x  = (const float*)d_in[0];
    // d_in[1] = mask (tril) — implemented analytically, unused
    const float* Wq = (const float*)d_in[2];
    const float* bq = (const float*)d_in[3];
    const float* Wk = (const float*)d_in[4];
    const float* bk = (const float*)d_in[5];
    const float* Wv = (const float*)d_in[6];
    const float* bv = (const float*)d_in[7];
    const float* Wo = (const float*)d_in[8];
    const float* bo = (const float*)d_in[9];
    float* out = (float*)d_out;

    float *pQ, *pK, *pV, *pP, *pC;
    cudaGetSymbolAddress((void**)&pQ, g_Q);
    cudaGetSymbolAddress((void**)&pK, g_K);
    cudaGetSymbolAddress((void**)&pV, g_V);
    cudaGetSymbolAddress((void**)&pP, g_P);
    cudaGetSymbolAddress((void**)&pC, g_C);

    const dim3 blk(256);
    const dim3 gProj(DD / BN, (BB * SS) / BM, 1);
    const dim3 gAttn(SS / BN, SS / BM, BB);

    // 1) Q/K/V projections with bias
    gemm_kernel<true><<<gProj, blk>>>(x, Wq, bq, pQ, BB * SS, DD, DD, 0, 0, 0, 1.f, 0, 0);
    gemm_kernel<true><<<gProj, blk>>>(x, Wk, bk, pK, BB * SS, DD, DD, 0, 0, 0, 1.f, 0, 0);
    gemm_kernel<true><<<gProj, blk>>>(x, Wv, bv, pV, BB * SS, DD, DD, 0, 0, 0, 1.f, 0, 0);

    // 2) RoPE on Q and K
    {
        const long long total = (long long)BB * SS * (DD / 2);
        const int nb = (int)((total + 255) / 256);
        rope_kernel<<<nb, 256>>>(pQ, pK);
    }

    // 3) Scores = Q K^T / sqrt(D), causal (lower-triangular tiles only)
    const float scale = 0.022097086912079608f;  // 1/sqrt(2048)
    gemm_kernel<true><<<gAttn, blk>>>(pQ, pK, nullptr, pP, SS, SS, DD,
                                      (long long)SS * DD, (long long)SS * DD,
                                      (long long)SS * SS, scale, 1, 0);

    // 4) Causal softmax (+ zero-fill to tile boundary)
    softmax_kernel<<<dim3(SS, BB), 256>>>(pP);

    // 5) ctx = P V, with triangular K limit per row tile
    gemm_kernel<false><<<gAttn, blk>>>(pP, pV, nullptr, pC, SS, DD, SS,
                                       (long long)SS * SS, (long long)SS * DD,
                                       (long long)SS * DD, 1.f, 0, 1);

    // 6) out = ctx Wo^T + bo
    gemm_kernel<true><<<gProj, blk>>>(pC, Wo, bo, out, BB * SS, DD, DD, 0, 0, 0, 1.f, 0, 0);
}

// round 3
// speedup vs baseline: 2.4665x; 2.4665x over previous
#include <cuda_runtime.h>
#include <cuda_bf16.h>
#include <math.h>
#include <stdint.h>

#define BB 4
#define SS 2048
#define DD 2048

constexpr int BM = 128, BN = 128, BK = 32;
constexpr int LDSU = 20;  // uint32 stride per smem row (= 40 bf16 = BK + 8 pad)

// Scratch (device globals — no allocations allowed)
__device__ float g_Q [(size_t)BB * SS * DD];
__device__ float g_K [(size_t)BB * SS * DD];
__device__ float g_Vt[(size_t)BB * SS * DD];   // V stored transposed: [b][d][s]
__device__ float g_P [(size_t)BB * SS * SS];
__device__ float g_C [(size_t)BB * SS * DD];
__device__ float g_invf[DD / 2];

// ---------------------------------------------------------------------------
// helpers
// ---------------------------------------------------------------------------
__device__ __forceinline__ void split_pack(float x, float y, uint32_t& hi, uint32_t& lo)
{
    __nv_bfloat16 hx = __float2bfloat16(x);
    __nv_bfloat16 hy = __float2bfloat16(y);
    float rx = x - __bfloat162float(hx);
    float ry = y - __bfloat162float(hy);
    __nv_bfloat162 h; h.x = hx; h.y = hy;
    __nv_bfloat162 l; l.x = __float2bfloat16(rx); l.y = __float2bfloat16(ry);
    hi = *reinterpret_cast<uint32_t*>(&h);
    lo = *reinterpret_cast<uint32_t*>(&l);
}

__device__ __forceinline__ void ldsm4(uint32_t* r, uint32_t addr)
{
    asm volatile("ldmatrix.sync.aligned.m8n8.x4.shared.b16 {%0,%1,%2,%3}, [%4];\n"
                 : "=r"(r[0]), "=r"(r[1]), "=r"(r[2]), "=r"(r[3])
                 : "r"(addr));
}

__device__ __forceinline__ void mma16816(float* d, const uint32_t* a, const uint32_t* b)
{
    asm volatile(
        "mma.sync.aligned.m16n8k16.row.col.f32.bf16.bf16.f32 "
        "{%0,%1,%2,%3}, {%4,%5,%6,%7}, {%8,%9}, {%0,%1,%2,%3};\n"
        : "+f"(d[0]), "+f"(d[1]), "+f"(d[2]), "+f"(d[3])
        : "r"(a[0]), "r"(a[1]), "r"(a[2]), "r"(a[3]), "r"(b[0]), "r"(b[1]));
}

// ---------------------------------------------------------------------------
// bf16-split tensor-core GEMM:
//   C[m,n] = sum_k A[m,k] * B[n,k]      (both A and B row stride = K)
// fp32 in gmem; converted to (hi,lo) bf16 pairs in smem; acc = Ah*Bh+Ah*Bl+Al*Bh.
// Flags: bias (per-n), scale, causal (skip/zero upper triangle), triK (kEnd=m0+BM),
// TRANSC (write C transposed per batch: C[b][n][m], for the V projection).
// ---------------------------------------------------------------------------
template <bool TRANSC>
__global__ __launch_bounds__(256, 2) void gemm_bf16s(
    const float* __restrict__ A, const float* __restrict__ B,
    const float* __restrict__ bias, float* __restrict__ C,
    int N, int K, long long sA, long long sB, long long sC,
    float scale, int causal, int triK)
{
    const int b = blockIdx.z;
    A += (long long)b * sA;
    B += (long long)b * sB;
    if (!TRANSC) C += (long long)b * sC;

    const int m0 = blockIdx.y * BM;
    const int n0 = blockIdx.x * BN;
    if (causal && n0 > m0 + BM - 1) return;
    const int kEnd = triK ? (m0 + BM) : K;

    __shared__ uint32_t sAh[BM * LDSU], sAl[BM * LDSU];
    __shared__ uint32_t sBh[BN * LDSU], sBl[BN * LDSU];

    const int t = threadIdx.x;
    const int lane = t & 31, warp = t >> 5;
    const int wm = warp >> 1;   // 0..3 -> 32 rows each
    const int wn = warp & 1;    // 0..1 -> 64 cols each

    float acc[2][8][4];
#pragma unroll
    for (int i = 0; i < 2; i++)
#pragma unroll
        for (int j = 0; j < 8; j++)
#pragma unroll
            for (int q = 0; q < 4; q++) acc[i][j][q] = 0.f;

    const uint32_t baseAh = (uint32_t)__cvta_generic_to_shared(sAh);
    const uint32_t baseAl = (uint32_t)__cvta_generic_to_shared(sAl);
    const uint32_t baseBh = (uint32_t)__cvta_generic_to_shared(sBh);
    const uint32_t baseBl = (uint32_t)__cvta_generic_to_shared(sBl);

    // ldmatrix lane->element offsets
    const int a_r = (lane & 7) + ((lane >> 3) & 1) * 8;  // row within 16 (m)
    const int a_c = (lane >> 4) * 8;                     // k half
    const int b_r = (lane & 7) + ((lane >> 4) & 1) * 8;  // row within 16 (n)
    const int b_c = ((lane >> 3) & 1) * 8;               // k half

    for (int k0 = 0; k0 < kEnd; k0 += BK) {
        // gmem (fp32) -> split -> smem (bf16 hi/lo)
#pragma unroll
        for (int i = 0; i < 4; i++) {
            const int idx = i * 256 + t;
            const int row = idx >> 3;
            const int kc = (idx & 7) * 4;
            const int so = row * LDSU + (kc >> 1);

            float4 va = *reinterpret_cast<const float4*>(
                &A[(long long)(m0 + row) * K + k0 + kc]);
            uint32_t h0, l0, h1, l1;
            split_pack(va.x, va.y, h0, l0);
            split_pack(va.z, va.w, h1, l1);
            sAh[so] = h0; sAh[so + 1] = h1;
            sAl[so] = l0; sAl[so + 1] = l1;

            float4 vb = *reinterpret_cast<const float4*>(
                &B[(long long)(n0 + row) * K + k0 + kc]);
            split_pack(vb.x, vb.y, h0, l0);
            split_pack(vb.z, vb.w, h1, l1);
            sBh[so] = h0; sBh[so + 1] = h1;
            sBl[so] = l0; sBl[so + 1] = l1;
        }
        __syncthreads();

#pragma unroll
        for (int kk = 0; kk < BK; kk += 16) {
            uint32_t ah[2][4], al[2][4];
#pragma unroll
            for (int mt = 0; mt < 2; mt++) {
                const int row = wm * 32 + mt * 16 + a_r;
                const uint32_t off = (uint32_t)(row * 40 + kk + a_c) * 2;
                ldsm4(ah[mt], baseAh + off);
                ldsm4(al[mt], baseAl + off);
            }
#pragma unroll
            for (int np = 0; np < 4; np++) {
                const int nrow = wn * 64 + np * 16 + b_r;
                const uint32_t off = (uint32_t)(nrow * 40 + kk + b_c) * 2;
                uint32_t bh[4], bl[4];
                ldsm4(bh, baseBh + off);
                ldsm4(bl, baseBl + off);
#pragma unroll
                for (int mt = 0; mt < 2; mt++) {
                    mma16816(acc[mt][2 * np],     ah[mt], bh);
                    mma16816(acc[mt][2 * np],     ah[mt], bl);
                    mma16816(acc[mt][2 * np],     al[mt], bh);
                    mma16816(acc[mt][2 * np + 1], ah[mt], bh + 2);
                    mma16816(acc[mt][2 * np + 1], ah[mt], bl + 2);
                    mma16816(acc[mt][2 * np + 1], al[mt], bh + 2);
                }
            }
        }
        __syncthreads();
    }

    // epilogue
#pragma unroll
    for (int mt = 0; mt < 2; mt++) {
        const int gi0 = m0 + wm * 32 + mt * 16 + (lane >> 2);
#pragma unroll
        for (int nt = 0; nt < 8; nt++) {
            const int gj = n0 + wn * 64 + nt * 8 + (lane & 3) * 2;
            const float* d = acc[mt][nt];
#pragma unroll
            for (int h = 0; h < 2; h++) {
                const int gi = gi0 + h * 8;
                float v0 = d[h * 2 + 0] * scale;
                float v1 = d[h * 2 + 1] * scale;
                if (bias) { v0 += bias[gj]; v1 += bias[gj + 1]; }
                if (causal) {
                    if (gj > gi) v0 = 0.f;
                    if (gj + 1 > gi) v1 = 0.f;
                }
                if (TRANSC) {
                    const int bb = gi >> 11;          // SS = 2048
                    const int s2 = gi & (SS - 1);
                    C[((long long)bb * DD + gj) * SS + s2] = v0;
                    C[((long long)bb * DD + gj + 1) * SS + s2] = v1;
                } else {
                    *reinterpret_cast<float2*>(&C[(long long)gi * N + gj]) =
                        make_float2(v0, v1);
                }
            }
        }
    }
}

// ---------------------------------------------------------------------------
// inv_freq table (double-precision exp, once per launch)
// ---------------------------------------------------------------------------
__global__ void invf_kernel(float* __restrict__ invf)
{
    const int i = blockIdx.x * blockDim.x + threadIdx.x;
    if (i < DD / 2)
        invf[i] = (float)exp(-(double)i * (9.210340371976184 / (double)(DD / 2)));
}

// ---------------------------------------------------------------------------
// RoPE: rotate (i, i+half) pairs of Q and K in place using the invf table.
// ---------------------------------------------------------------------------
__global__ void rope_kernel(float* __restrict__ Q, float* __restrict__ Kt,
                            const float* __restrict__ invf)
{
    const int half = DD / 2;
    long long idx = (long long)blockIdx.x * blockDim.x + threadIdx.x;
    const long long total = (long long)BB * SS * half;
    if (idx >= total) return;

    const int i = (int)(idx % half);
    const long long bs = idx / half;
    const int s = (int)(bs % SS);

    const float ang = (float)s * invf[i];
    float sn, cs;
    sincosf(ang, &sn, &cs);

    float* q = Q + bs * DD;
    float* k = Kt + bs * DD;

    const float q1 = q[i], q2 = q[i + half];
    q[i] = q1 * cs - q2 * sn;
    q[i + half] = q1 * sn + q2 * cs;

    const float k1 = k[i], k2 = k[i + half];
    k[i] = k1 * cs - k2 * sn;
    k[i + half] = k1 * sn + k2 * cs;
}

// ---------------------------------------------------------------------------
// Causal row softmax over j <= i, then zero-fill up to the 128 boundary.
// ---------------------------------------------------------------------------
__inline__ __device__ float warpMax(float v)
{
    for (int o = 16; o; o >>= 1) v = fmaxf(v, __shfl_xor_sync(0xffffffffu, v, o));
    return v;
}
__inline__ __device__ float warpSum(float v)
{
    for (int o = 16; o; o >>= 1) v += __shfl_xor_sync(0xffffffffu, v, o);
    return v;
}

__global__ __launch_bounds__(256) void softmax_kernel(float* __restrict__ P)
{
    const int i = blockIdx.x;
    const int b = blockIdx.y;
    float* row = P + ((long long)b * SS + i) * SS;
    const int len = i + 1;
    const int t = threadIdx.x;
    const int lane = t & 31, w = t >> 5;

    __shared__ float sh[8];
    __shared__ float s_bcast;

    float m = -INFINITY;
    for (int j = t; j < len; j += 256) m = fmaxf(m, row[j]);
    m = warpMax(m);
    if (lane == 0) sh[w] = m;
    __syncthreads();
    if (t == 0) {
        float mm = sh[0];
        for (int k = 1; k < 8; k++) mm = fmaxf(mm, sh[k]);
        s_bcast = mm;
    }
    __syncthreads();
    m = s_bcast;
    __syncthreads();

    float sum = 0.f;
    for (int j = t; j < len; j += 256) {
        const float e = expf(row[j] - m);
        row[j] = e;
        sum += e;
    }
    sum = warpSum(sum);
    if (lane == 0) sh[w] = sum;
    __syncthreads();
    if (t == 0) {
        float ss = 0.f;
        for (int k = 0; k < 8; k++) ss += sh[k];
        s_bcast = ss;
    }
    __syncthreads();
    const float inv = 1.f / s_bcast;

    for (int j = t; j < len; j += 256) row[j] *= inv;
    const int kend = ((i >> 7) + 1) << 7;
    for (int j = len + t; j < kend; j += 256) row[j] = 0.f;
}

// ---------------------------------------------------------------------------
extern "C" void kernel_launch(void* const* d_in, const int* in_sizes, int n_in,
                              void* d_out, int out_size)
{
    const float* x  = (const float*)d_in[0];
    // d_in[1] = mask (tril) — analytic, unused
    const float* Wq = (const float*)d_in[2];
    const float* bq = (const float*)d_in[3];
    const float* Wk = (const float*)d_in[4];
    const float* bk = (const float*)d_in[5];
    const float* Wv = (const float*)d_in[6];
    const float* bv = (const float*)d_in[7];
    const float* Wo = (const float*)d_in[8];
    const float* bo = (const float*)d_in[9];
    float* out = (float*)d_out;

    float *pQ, *pK, *pVt, *pP, *pC, *pInvf;
    cudaGetSymbolAddress((void**)&pQ, g_Q);
    cudaGetSymbolAddress((void**)&pK, g_K);
    cudaGetSymbolAddress((void**)&pVt, g_Vt);
    cudaGetSymbolAddress((void**)&pP, g_P);
    cudaGetSymbolAddress((void**)&pC, g_C);
    cudaGetSymbolAddress((void**)&pInvf, g_invf);

    const dim3 blk(256);
    const dim3 gProj(DD / BN, (BB * SS) / BM, 1);
    const dim3 gAttn(SS / BN, SS / BM, BB);

    invf_kernel<<<(DD / 2 + 255) / 256, 256>>>(pInvf);

    // 1) Q/K projections (+bias); V projection written transposed
    gemm_bf16s<false><<<gProj, blk>>>(x, Wq, bq, pQ,  DD, DD, 0, 0, 0, 1.f, 0, 0);
    gemm_bf16s<false><<<gProj, blk>>>(x, Wk, bk, pK,  DD, DD, 0, 0, 0, 1.f, 0, 0);
    gemm_bf16s<true ><<<gProj, blk>>>(x, Wv, bv, pVt, DD, DD, 0, 0, 0, 1.f, 0, 0);

    // 2) RoPE on Q and K
    {
        const long long total = (long long)BB * SS * (DD / 2);
        rope_kernel<<<(int)((total + 255) / 256), 256>>>(pQ, pK, pInvf);
    }

    // 3) scores = Q K^T / sqrt(D), causal
    const float scale = 0.022097086912079608f;  // 1/sqrt(2048)
    gemm_bf16s<false><<<gAttn, blk>>>(pQ, pK, nullptr, pP, SS, DD,
                                      (long long)SS * DD, (long long)SS * DD,
                                      (long long)SS * SS, scale, 1, 0);

    // 4) causal softmax
    softmax_kernel<<<dim3(SS, BB), 256>>>(pP);

    // 5) ctx = P V  (B = Vt[n=d][k=s], triangular K limit)
    gemm_bf16s<false><<<gAttn, blk>>>(pP, pVt, nullptr, pC, DD, SS,
                                      (long long)SS * SS, (long long)SS * DD,
                                      (long long)SS * DD, 1.f, 0, 1);

    // 6) out = ctx Wo^T + bo
    gemm_bf16s<false><<<gProj, blk>>>(pC, Wo, bo, out, DD, DD, 0, 0, 0, 1.f, 0, 0);
}

// round 6
// speedup vs baseline: 2.8183x; 1.1426x over previous
#include <cuda_runtime.h>
#include <cuda_bf16.h>
#include <math.h>
#include <stdint.h>

#define BB 4
#define SS 2048
#define DD 2048
typedef __nv_bfloat16 bf16;

constexpr int BM = 128, BN = 128, BK = 32;
constexpr int ROWB = 80;                    // bytes per smem row (32 bf16 + 16B pad)
constexpr int TILE_B = 128 * ROWB;          // 10240 bytes per sub-tile
constexpr int STAGE = 4 * TILE_B;           // Ah, Al, Bh, Bl
constexpr int SMEM_TOTAL = 2 * STAGE;       // 81920

// ---------------------------------------------------------------------------
// Scratch (device globals — no allocations allowed)
// ---------------------------------------------------------------------------
__device__ float g_Q [(size_t)BB * SS * DD];
__device__ float g_K [(size_t)BB * SS * DD];
__device__ float g_P [(size_t)BB * SS * SS];
__device__ float g_invf[DD / 2];

__device__ bf16 g_xh [(size_t)BB * SS * DD], g_xl [(size_t)BB * SS * DD];
__device__ bf16 g_Wqh[(size_t)DD * DD],      g_Wql[(size_t)DD * DD];
__device__ bf16 g_Wkh[(size_t)DD * DD],      g_Wkl[(size_t)DD * DD];
__device__ bf16 g_Wvh[(size_t)DD * DD],      g_Wvl[(size_t)DD * DD];
__device__ bf16 g_Woh[(size_t)DD * DD],      g_Wol[(size_t)DD * DD];
__device__ bf16 g_Qh [(size_t)BB * SS * DD], g_Ql [(size_t)BB * SS * DD];
__device__ bf16 g_Kh [(size_t)BB * SS * DD], g_Kl [(size_t)BB * SS * DD];
__device__ bf16 g_Vth[(size_t)BB * SS * DD], g_Vtl[(size_t)BB * SS * DD];  // [b][d][s]
__device__ bf16 g_Ph [(size_t)BB * SS * SS], g_Pl [(size_t)BB * SS * SS];
__device__ bf16 g_Ch [(size_t)BB * SS * DD], g_Cl [(size_t)BB * SS * DD];

// ---------------------------------------------------------------------------
// helpers
// ---------------------------------------------------------------------------
__device__ __forceinline__ uint32_t smem_u32(const void* p)
{
    uint32_t a;
    asm("{ .reg .u64 t; cvta.to.shared.u64 t, %1; cvt.u32.u64 %0, t; }"
        : "=r"(a) : "l"(p));
    return a;
}
__device__ __forceinline__ void cp16(uint32_t saddr, const void* g)
{
    asm volatile("cp.async.cg.shared.global [%0], [%1], 16;" :: "r"(saddr), "l"(g));
}
__device__ __forceinline__ void cp_commit() { asm volatile("cp.async.commit_group;"); }
__device__ __forceinline__ void cp_wait1()  { asm volatile("cp.async.wait_group 1;"); }
__device__ __forceinline__ void cp_wait0()  { asm volatile("cp.async.wait_group 0;"); }

__device__ __forceinline__ void ldsm4(uint32_t* r, uint32_t addr)
{
    asm volatile("ldmatrix.sync.aligned.m8n8.x4.shared.b16 {%0,%1,%2,%3}, [%4];\n"
                 : "=r"(r[0]), "=r"(r[1]), "=r"(r[2]), "=r"(r[3]) : "r"(addr));
}
__device__ __forceinline__ void mma16816(float* d, const uint32_t* a, const uint32_t* b)
{
    asm volatile(
        "mma.sync.aligned.m16n8k16.row.col.f32.bf16.bf16.f32 "
        "{%0,%1,%2,%3}, {%4,%5,%6,%7}, {%8,%9}, {%0,%1,%2,%3};\n"
        : "+f"(d[0]), "+f"(d[1]), "+f"(d[2]), "+f"(d[3])
        : "r"(a[0]), "r"(a[1]), "r"(a[2]), "r"(a[3]), "r"(b[0]), "r"(b[1]));
}
__device__ __forceinline__ void split1(float v, bf16& h, bf16& l)
{
    h = __float2bfloat16(v);
    l = __float2bfloat16(v - __bfloat162float(h));
}

// ---------------------------------------------------------------------------
// Pre-split bf16 GEMM:  C[m,n] = sum_k A[m,k]*B[n,k]
//   A = (Ah,Al), B = (Bh,Bl) bf16 hi/lo, k-contiguous, row stride K.
//   acc = Ah*Bh + Ah*Bl + Al*Bh (fp32 regs).
// EPI: 0 = fp32 C (+bias/scale/causal-zero), 1 = split bf16 (Ch,Cl),
//      2 = split + transpose per batch (Ch,Cl as [b][n][m], for Vt) with bias.
// ---------------------------------------------------------------------------
template <int EPI>
__global__ __launch_bounds__(256, 2) void gemm_pre(
    const bf16* __restrict__ Ah, const bf16* __restrict__ Al,
    const bf16* __restrict__ Bh, const bf16* __restrict__ Bl,
    const float* __restrict__ bias, float* __restrict__ C,
    bf16* __restrict__ Ch, bf16* __restrict__ Cl,
    int N, int K, long long sA, long long sB, long long sC,
    float scale, int causal, int triK)
{
    extern __shared__ __align__(128) char dsm[];
    const uint32_t smem_base = smem_u32(dsm);

    const int b = blockIdx.z;
    Ah += (long long)b * sA;  Al += (long long)b * sA;
    Bh += (long long)b * sB;  Bl += (long long)b * sB;
    if (EPI == 0) C += (long long)b * sC;
    if (EPI == 1) { Ch += (long long)b * sC; Cl += (long long)b * sC; }

    const int m0 = blockIdx.y * BM;
    const int n0 = blockIdx.x * BN;
    if (causal && n0 > m0 + BM - 1) return;
    const int kEnd = triK ? (m0 + BM) : K;
    const int nSteps = kEnd / BK;

    const int t = threadIdx.x;
    const int lane = t & 31, warp = t >> 5;
    const int wm = warp >> 1;   // 0..3 -> 32 rows
    const int wn = warp & 1;    // 0..1 -> 64 cols

    float acc[2][8][4];
#pragma unroll
    for (int i = 0; i < 2; i++)
#pragma unroll
        for (int j = 0; j < 8; j++)
#pragma unroll
            for (int q = 0; q < 4; q++) acc[i][j][q] = 0.f;

    // fill one stage: 512 16B-chunks per sub-tile, 2 per thread per sub-tile
    auto fill = [&](int buf, int ks) {
        const int k0 = ks * BK;
        const uint32_t sb = smem_base + buf * STAGE;
#pragma unroll
        for (int p = 0; p < 2; p++) {
            const int idx = p * 256 + t;
            const int row = idx >> 2;
            const int ch = idx & 3;
            const uint32_t so = (uint32_t)(row * ROWB + ch * 16);
            const long long ga = (long long)(m0 + row) * K + k0 + ch * 8;
            const long long gb = (long long)(n0 + row) * K + k0 + ch * 8;
            cp16(sb + 0 * TILE_B + so, Ah + ga);
            cp16(sb + 1 * TILE_B + so, Al + ga);
            cp16(sb + 2 * TILE_B + so, Bh + gb);
            cp16(sb + 3 * TILE_B + so, Bl + gb);
        }
    };

    // ldmatrix lane->element offsets (validated layout from R2/R3)
    const int a_r = (lane & 7) + ((lane >> 3) & 1) * 8;
    const int a_c = (lane >> 4) * 8;
    const int b_r = (lane & 7) + ((lane >> 4) & 1) * 8;
    const int b_c = ((lane >> 3) & 1) * 8;

    fill(0, 0); cp_commit();
    fill(1, 1); cp_commit();

    for (int ks = 0; ks < nSteps; ks++) {
        cp_wait1();
        __syncthreads();

        const uint32_t sb = smem_base + (ks & 1) * STAGE;
        const uint32_t bAh = sb, bAl = sb + TILE_B;
        const uint32_t bBh = sb + 2 * TILE_B, bBl = sb + 3 * TILE_B;

#pragma unroll
        for (int kk = 0; kk < BK; kk += 16) {
            uint32_t ah[2][4], al[2][4];
#pragma unroll
            for (int mt = 0; mt < 2; mt++) {
                const int row = wm * 32 + mt * 16 + a_r;
                const uint32_t off = (uint32_t)(row * ROWB + (kk + a_c) * 2);
                ldsm4(ah[mt], bAh + off);
                ldsm4(al[mt], bAl + off);
            }
#pragma unroll
            for (int np = 0; np < 4; np++) {
                const int nrow = wn * 64 + np * 16 + b_r;
                const uint32_t off = (uint32_t)(nrow * ROWB + (kk + b_c) * 2);
                uint32_t bh[4], bl[4];
                ldsm4(bh, bBh + off);
                ldsm4(bl, bBl + off);
#pragma unroll
                for (int mt = 0; mt < 2; mt++) {
                    mma16816(acc[mt][2 * np],     ah[mt], bh);
                    mma16816(acc[mt][2 * np],     ah[mt], bl);
                    mma16816(acc[mt][2 * np],     al[mt], bh);
                    mma16816(acc[mt][2 * np + 1], ah[mt], bh + 2);
                    mma16816(acc[mt][2 * np + 1], ah[mt], bl + 2);
                    mma16816(acc[mt][2 * np + 1], al[mt], bh + 2);
                }
            }
        }
        __syncthreads();
        if (ks + 2 < nSteps) fill(ks & 1, ks + 2);
        cp_commit();
    }

    // ---------------- epilogue ----------------
    if (EPI == 2) {
        // transpose through smem, then coalesced write of Vt hi/lo
        cp_wait0();
        __syncthreads();
        bf16* Th = reinterpret_cast<bf16*>(dsm);              // [128][136]
        bf16* Tl = Th + 128 * 136;
#pragma unroll
        for (int mt = 0; mt < 2; mt++) {
            const int li0 = wm * 32 + mt * 16 + (lane >> 2);
#pragma unroll
            for (int nt = 0; nt < 8; nt++) {
                const int lj = wn * 64 + nt * 8 + (lane & 3) * 2;
#pragma unroll
                for (int h = 0; h < 2; h++) {
                    const int li = li0 + h * 8;
#pragma unroll
                    for (int c = 0; c < 2; c++) {
                        float v = acc[mt][nt][h * 2 + c];
                        if (bias) v += bias[n0 + lj + c];
                        bf16 hh, ll;
                        split1(v, hh, ll);
                        Th[(lj + c) * 136 + li] = hh;
                        Tl[(lj + c) * 136 + li] = ll;
                    }
                }
            }
        }
        __syncthreads();
        {
            const int arr = t >> 7;          // 0 = hi, 1 = lo
            const int j = t & 127;           // local n (= d) row
            const int bb = m0 >> 11;
            const int s0 = m0 & (SS - 1);
            const bf16* src = (arr ? Tl : Th) + j * 136;
            bf16* dst = (arr ? Cl : Ch) + ((long long)bb * DD + n0 + j) * SS + s0;
#pragma unroll
            for (int i = 0; i < 128; i += 8)
                *reinterpret_cast<uint4*>(dst + i) =
                    *reinterpret_cast<const uint4*>(src + i);
        }
        return;
    }

#pragma unroll
    for (int mt = 0; mt < 2; mt++) {
        const int gi0 = m0 + wm * 32 + mt * 16 + (lane >> 2);
#pragma unroll
        for (int nt = 0; nt < 8; nt++) {
            const int gj = n0 + wn * 64 + nt * 8 + (lane & 3) * 2;
            const float* d = acc[mt][nt];
#pragma unroll
            for (int h = 0; h < 2; h++) {
                const int gi = gi0 + h * 8;
                float v0 = d[h * 2 + 0] * scale;
                float v1 = d[h * 2 + 1] * scale;
                if (bias) { v0 += bias[gj]; v1 += bias[gj + 1]; }
                if (causal) {
                    if (gj > gi) v0 = 0.f;
                    if (gj + 1 > gi) v1 = 0.f;
                }
                if (EPI == 0) {
                    *reinterpret_cast<float2*>(&C[(long long)gi * N + gj]) =
                        make_float2(v0, v1);
                } else {
                    bf16 h0, l0, h1, l1;
                    split1(v0, h0, l0);
                    split1(v1, h1, l1);
                    __nv_bfloat162 ph; ph.x = h0; ph.y = h1;
                    __nv_bfloat162 pl; pl.x = l0; pl.y = l1;
                    *reinterpret_cast<__nv_bfloat162*>(&Ch[(long long)gi * N + gj]) = ph;
                    *reinterpret_cast<__nv_bfloat162*>(&Cl[(long long)gi * N + gj]) = pl;
                }
            }
        }
    }
}

// ---------------------------------------------------------------------------
// split kernel: fp32 -> bf16 hi/lo  (4 elements per thread)
// ---------------------------------------------------------------------------
__global__ void split_kernel(const float* __restrict__ src,
                             bf16* __restrict__ dh, bf16* __restrict__ dl,
                             long long n4)
{
    const long long i = (long long)blockIdx.x * blockDim.x + threadIdx.x;
    if (i >= n4) return;
    float4 v = *reinterpret_cast<const float4*>(src + i * 4);
    bf16 h[4], l[4];
    split1(v.x, h[0], l[0]); split1(v.y, h[1], l[1]);
    split1(v.z, h[2], l[2]); split1(v.w, h[3], l[3]);
    *reinterpret_cast<uint2*>(dh + i * 4) = *reinterpret_cast<uint2*>(h);
    *reinterpret_cast<uint2*>(dl + i * 4) = *reinterpret_cast<uint2*>(l);
}

// ---------------------------------------------------------------------------
__global__ void invf_kernel(float* __restrict__ invf)
{
    const int i = blockIdx.x * blockDim.x + threadIdx.x;
    if (i < DD / 2)
        invf[i] = (float)exp(-(double)i * (9.210340371976184 / (double)(DD / 2)));
}

// ---------------------------------------------------------------------------
// RoPE: rotate fp32 Q/K pairs, emit bf16 hi/lo splits (no fp32 writeback).
// ---------------------------------------------------------------------------
__global__ void rope_split_kernel(const float* __restrict__ Q,
                                  const float* __restrict__ Kt,
                                  const float* __restrict__ invf,
                                  bf16* __restrict__ Qh, bf16* __restrict__ Ql,
                                  bf16* __restrict__ Kh, bf16* __restrict__ Kl)
{
    const int half = DD / 2;
    long long idx = (long long)blockIdx.x * blockDim.x + threadIdx.x;
    const long long total = (long long)BB * SS * half;
    if (idx >= total) return;

    const int i = (int)(idx % half);
    const long long bs = idx / half;
    const int s = (int)(bs % SS);

    const float ang = (float)s * invf[i];
    float sn, cs;
    sincosf(ang, &sn, &cs);

    const long long o = bs * DD;
    const float q1 = Q[o + i], q2 = Q[o + i + half];
    const float k1 = Kt[o + i], k2 = Kt[o + i + half];
    const float qa = q1 * cs - q2 * sn, qb = q1 * sn + q2 * cs;
    const float ka = k1 * cs - k2 * sn, kb = k1 * sn + k2 * cs;

    bf16 h, l;
    split1(qa, h, l); Qh[o + i] = h;        Ql[o + i] = l;
    split1(qb, h, l); Qh[o + i + half] = h; Ql[o + i + half] = l;
    split1(ka, h, l); Kh[o + i] = h;        Kl[o + i] = l;
    split1(kb, h, l); Kh[o + i + half] = h; Kl[o + i + half] = l;
}

// ---------------------------------------------------------------------------
// Causal softmax over fp32 scores; emits bf16 hi/lo P (+ zero-fill to 128).
// ---------------------------------------------------------------------------
__inline__ __device__ float warpMax(float v)
{
    for (int o = 16; o; o >>= 1) v = fmaxf(v, __shfl_xor_sync(0xffffffffu, v, o));
    return v;
}
__inline__ __device__ float warpSum(float v)
{
    for (int o = 16; o; o >>= 1) v += __shfl_xor_sync(0xffffffffu, v, o);
    return v;
}

__global__ __launch_bounds__(256) void softmax_split_kernel(
    float* __restrict__ P, bf16* __restrict__ Ph, bf16* __restrict__ Pl)
{
    const int i = blockIdx.x;
    const int b = blockIdx.y;
    const long long off = ((long long)b * SS + i) * SS;
    float* row = P + off;
    const int len = i + 1;
    const int t = threadIdx.x;
    const int lane = t & 31, w = t >> 5;

    __shared__ float sh[8];
    __shared__ float s_bcast;

    float m = -INFINITY;
    for (int j = t; j < len; j += 256) m = fmaxf(m, row[j]);
    m = warpMax(m);
    if (lane == 0) sh[w] = m;
    __syncthreads();
    if (t == 0) {
        float mm = sh[0];
        for (int k = 1; k < 8; k++) mm = fmaxf(mm, sh[k]);
        s_bcast = mm;
    }
    __syncthreads();
    m = s_bcast;
    __syncthreads();

    float sum = 0.f;
    for (int j = t; j < len; j += 256) {
        const float e = expf(row[j] - m);
        row[j] = e;
        sum += e;
    }
    sum = warpSum(sum);
    if (lane == 0) sh[w] = sum;
    __syncthreads();
    if (t == 0) {
        float ss = 0.f;
        for (int k = 0; k < 8; k++) ss += sh[k];
        s_bcast = ss;
    }
    __syncthreads();
    const float inv = 1.f / s_bcast;

    for (int j = t; j < len; j += 256) {
        bf16 h, l;
        split1(row[j] * inv, h, l);
        Ph[off + j] = h;
        Pl[off + j] = l;
    }
    const int kend = ((i >> 7) + 1) << 7;
    const bf16 z = __float2bfloat16(0.f);
    for (int j = len + t; j < kend; j += 256) { Ph[off + j] = z; Pl[off + j] = z; }
}

// ---------------------------------------------------------------------------
extern "C" void kernel_launch(void* const* d_in, const int* in_sizes, int n_in,
                              void* d_out, int out_size)
{
    const float* x  = (const float*)d_in[0];
    // d_in[1] = mask — analytic
    const float* Wq = (const float*)d_in[2];
    const float* bq = (const float*)d_in[3];
    const float* Wk = (const float*)d_in[4];
    const float* bk = (const float*)d_in[5];
    const float* Wv = (const float*)d_in[6];
    const float* bv = (const float*)d_in[7];
    const float* Wo = (const float*)d_in[8];
    const float* bo = (const float*)d_in[9];
    float* out = (float*)d_out;

    float *pQ, *pK, *pP, *pInvf;
    cudaGetSymbolAddress((void**)&pQ, g_Q);
    cudaGetSymbolAddress((void**)&pK, g_K);
    cudaGetSymbolAddress((void**)&pP, g_P);
    cudaGetSymbolAddress((void**)&pInvf, g_invf);

    bf16 *xh, *xl, *Wqh, *Wql, *Wkh, *Wkl, *Wvh, *Wvl, *Woh, *Wol;
    bf16 *Qh, *Ql, *Kh, *Kl, *Vth, *Vtl, *Ph, *Pl, *Chh, *Cll;
    cudaGetSymbolAddress((void**)&xh, g_xh);   cudaGetSymbolAddress((void**)&xl, g_xl);
    cudaGetSymbolAddress((void**)&Wqh, g_Wqh); cudaGetSymbolAddress((void**)&Wql, g_Wql);
    cudaGetSymbolAddress((void**)&Wkh, g_Wkh); cudaGetSymbolAddress((void**)&Wkl, g_Wkl);
    cudaGetSymbolAddress((void**)&Wvh, g_Wvh); cudaGetSymbolAddress((void**)&Wvl, g_Wvl);
    cudaGetSymbolAddress((void**)&Woh, g_Woh); cudaGetSymbolAddress((void**)&Wol, g_Wol);
    cudaGetSymbolAddress((void**)&Qh, g_Qh);   cudaGetSymbolAddress((void**)&Ql, g_Ql);
    cudaGetSymbolAddress((void**)&Kh, g_Kh);   cudaGetSymbolAddress((void**)&Kl, g_Kl);
    cudaGetSymbolAddress((void**)&Vth, g_Vth); cudaGetSymbolAddress((void**)&Vtl, g_Vtl);
    cudaGetSymbolAddress((void**)&Ph, g_Ph);   cudaGetSymbolAddress((void**)&Pl, g_Pl);
    cudaGetSymbolAddress((void**)&Chh, g_Ch);  cudaGetSymbolAddress((void**)&Cll, g_Cl);

    cudaFuncSetAttribute(gemm_pre<0>, cudaFuncAttributeMaxDynamicSharedMemorySize, SMEM_TOTAL);
    cudaFuncSetAttribute(gemm_pre<1>, cudaFuncAttributeMaxDynamicSharedMemorySize, SMEM_TOTAL);
    cudaFuncSetAttribute(gemm_pre<2>, cudaFuncAttributeMaxDynamicSharedMemorySize, SMEM_TOTAL);

    const dim3 blk(256);
    const dim3 gProj(DD / BN, (BB * SS) / BM, 1);
    const dim3 gAttn(SS / BN, SS / BM, BB);

    invf_kernel<<<(DD / 2 + 255) / 256, 256>>>(pInvf);

    // 0) pre-split x and weights
    {
        const long long nx4 = (long long)BB * SS * DD / 4;
        split_kernel<<<(int)((nx4 + 255) / 256), 256>>>(x, xh, xl, nx4);
        const long long nw4 = (long long)DD * DD / 4;
        const int gw = (int)((nw4 + 255) / 256);
        split_kernel<<<gw, 256>>>(Wq, Wqh, Wql, nw4);
        split_kernel<<<gw, 256>>>(Wk, Wkh, Wkl, nw4);
        split_kernel<<<gw, 256>>>(Wv, Wvh, Wvl, nw4);
        split_kernel<<<gw, 256>>>(Wo, Woh, Wol, nw4);
    }

    // 1) projections: Q,K -> fp32 (rope consumes); V -> split+transposed
    gemm_pre<0><<<gProj, blk, SMEM_TOTAL>>>(xh, xl, Wqh, Wql, bq, pQ, nullptr, nullptr,
                                            DD, DD, 0, 0, 0, 1.f, 0, 0);
    gemm_pre<0><<<gProj, blk, SMEM_TOTAL>>>(xh, xl, Wkh, Wkl, bk, pK, nullptr, nullptr,
                                            DD, DD, 0, 0, 0, 1.f, 0, 0);
    gemm_pre<2><<<gProj, blk, SMEM_TOTAL>>>(xh, xl, Wvh, Wvl, bv, nullptr, Vth, Vtl,
                                            DD, DD, 0, 0, 0, 1.f, 0, 0);

    // 2) RoPE + split Q/K
    {
        const long long total = (long long)BB * SS * (DD / 2);
        rope_split_kernel<<<(int)((total + 255) / 256), 256>>>(pQ, pK, pInvf,
                                                               Qh, Ql, Kh, Kl);
    }

    // 3) scores = Q K^T / sqrt(D), causal -> fp32 P
    const float scale = 0.022097086912079608f;  // 1/sqrt(2048)
    gemm_pre<0><<<gAttn, blk, SMEM_TOTAL>>>(Qh, Ql, Kh, Kl, nullptr, pP, nullptr, nullptr,
                                            SS, DD, (long long)SS * DD, (long long)SS * DD,
                                            (long long)SS * SS, scale, 1, 0);

    // 4) softmax -> split P (+zero-fill)
    softmax_split_kernel<<<dim3(SS, BB), 256>>>(pP, Ph, Pl);

    // 5) ctx = P V (triangular K) -> split ctx
    gemm_pre<1><<<gAttn, blk, SMEM_TOTAL>>>(Ph, Pl, Vth, Vtl, nullptr, nullptr, Chh, Cll,
                                            DD, SS, (long long)SS * SS, (long long)SS * DD,
                                            (long long)SS * DD, 1.f, 0, 1);

    // 6) out = ctx Wo^T + bo
    gemm_pre<0><<<gProj, blk, SMEM_TOTAL>>>(Chh, Cll, Woh, Wol, bo, out, nullptr, nullptr,
                                            DD, DD, 0, 0, 0, 1.f, 0, 0);
}